// round 2
// baseline (speedup 1.0000x reference)
#include <cuda_runtime.h>
#include <math.h>

#define BB 8
#define TT 2048
#define EE 1024
#define HH 128
#define BT (BB*TT)

// ---------------- scratch (device globals: allocation-free) ----------------
__device__ float g_k[BT*HH];
__device__ float g_q[BT*HH];
__device__ float g_v[BT*HH];
__device__ float g_S[(size_t)BB*TT*TT];          // 134 MB score scratch
__device__ float g_pmax[8*BT];
__device__ float g_psum[8*BT];
__device__ float g_cmax[BT];
__device__ float g_crcp[BT];

// packed fp32x2 FMA: d.xy += a.xy * b.xy  (one SASS FFMA2 issue, 2 FMA lanes)
__device__ __forceinline__ void ffma2(unsigned long long& d,
                                      unsigned long long a,
                                      unsigned long long b) {
    asm("fma.rn.f32x2 %0, %1, %2, %0;" : "+l"(d) : "l"(a), "l"(b));
}

// ---------------- K1: q/k/v = x @ W  (M=BT, K=E, N=H) ----------------------
// block 256, tile 64(M) x 128(N), BK=16, micro 8x4 via f32x2 pairs
__global__ void qkv_kernel(const float* __restrict__ x,
                           const float* __restrict__ Wk,
                           const float* __restrict__ Wq,
                           const float* __restrict__ Wv) {
    const float* W   = (blockIdx.y == 0) ? Wk : (blockIdx.y == 1) ? Wq : Wv;
    float*       out = (blockIdx.y == 0) ? g_k : (blockIdx.y == 1) ? g_q : g_v;

    __shared__ float2 xs2[64][18];   // duplicated-pair A operand
    __shared__ float  ws[16][128];   // B operand, contiguous in N

    int tid = threadIdx.x;
    int tx = tid & 31;      // 32 groups of 4 cols -> 128
    int ty = tid >> 5;      // 8 groups of 8 rows  -> 64
    int m0 = blockIdx.x * 64;

    unsigned long long acc[8][2];
#pragma unroll
    for (int i = 0; i < 8; i++) { acc[i][0] = 0ull; acc[i][1] = 0ull; }

    for (int k0 = 0; k0 < EE; k0 += 16) {
        {   // x tile 64x16, dup-packed: one float4 load -> two float4 stores
            int r = tid >> 2, c4 = tid & 3;
            float4 v = *(const float4*)&x[(size_t)(m0 + r) * EE + k0 + c4 * 4];
            *(float4*)&xs2[r][c4 * 4]     = make_float4(v.x, v.x, v.y, v.y);
            *(float4*)&xs2[r][c4 * 4 + 2] = make_float4(v.z, v.z, v.w, v.w);
        }
#pragma unroll
        for (int i = 0; i < 2; i++) {  // W tile 16x128
            int idx = tid * 2 + i;
            int r = idx >> 5, c4 = idx & 31;
            *(float4*)&ws[r][c4 * 4] = *(const float4*)&W[(size_t)(k0 + r) * HH + c4 * 4];
        }
        __syncthreads();
#pragma unroll
        for (int kk = 0; kk < 16; kk++) {
            ulonglong2 b = *(const ulonglong2*)&ws[kk][tx * 4];
#pragma unroll
            for (int i = 0; i < 8; i++) {
                unsigned long long a = *(const unsigned long long*)&xs2[ty * 8 + i][kk];
                ffma2(acc[i][0], a, b.x);
                ffma2(acc[i][1], a, b.y);
            }
        }
        __syncthreads();
    }
#pragma unroll
    for (int i = 0; i < 8; i++) {
        int row = m0 + ty * 8 + i;
        float2 p0 = *reinterpret_cast<float2*>(&acc[i][0]);
        float2 p1 = *reinterpret_cast<float2*>(&acc[i][1]);
        *(float4*)&out[(size_t)row * HH + tx * 4] = make_float4(p0.x, p0.y, p1.x, p1.y);
    }
}

// ---------------- K2: S[b,t,s] = sqrt(H) * q[b,t] . k[b,s] -----------------
// block 256, tile 128(t) x 64(s), K=H chunks 16, micro 8x4 via f32x2
__global__ void score_kernel() {
    int t0 = blockIdx.x * 128;
    int s0 = blockIdx.y * 64;
    int b  = blockIdx.z;
    if (t0 + 127 < s0) return;             // tile fully above diagonal

    __shared__ float2 qs2[128][18];        // dup-packed A (q)
    __shared__ float  ks_t[16][68];        // B (k) transposed: [kk][s]

    const float* qb = g_q + (size_t)b * TT * HH;
    const float* kb = g_k + (size_t)b * TT * HH;

    int tid = threadIdx.x;
    int tx = tid & 15;      // 16 groups * 4 cols = 64 (s)
    int ty = tid >> 4;      // 16 groups * 8 rows = 128 (t)

    unsigned long long acc[8][2];
#pragma unroll
    for (int i = 0; i < 8; i++) { acc[i][0] = 0ull; acc[i][1] = 0ull; }

    for (int h0 = 0; h0 < HH; h0 += 16) {
#pragma unroll
        for (int i = 0; i < 2; i++) {   // q tile 128x16 dup-packed
            int idx = tid * 2 + i;
            int r = idx >> 2, c4 = idx & 3;
            float4 v = *(const float4*)&qb[(size_t)(t0 + r) * HH + h0 + c4 * 4];
            *(float4*)&qs2[r][c4 * 4]     = make_float4(v.x, v.x, v.y, v.y);
            *(float4*)&qs2[r][c4 * 4 + 2] = make_float4(v.z, v.z, v.w, v.w);
        }
        {   // k tile 64x16 -> transposed [kk][s]
            int r = tid >> 2, c4 = tid & 3;
            float4 v = *(const float4*)&kb[(size_t)(s0 + r) * HH + h0 + c4 * 4];
            ks_t[c4 * 4 + 0][r] = v.x;
            ks_t[c4 * 4 + 1][r] = v.y;
            ks_t[c4 * 4 + 2][r] = v.z;
            ks_t[c4 * 4 + 3][r] = v.w;
        }
        __syncthreads();
#pragma unroll
        for (int kk = 0; kk < 16; kk++) {
            ulonglong2 b2 = *(const ulonglong2*)&ks_t[kk][tx * 4];
#pragma unroll
            for (int i = 0; i < 8; i++) {
                unsigned long long a = *(const unsigned long long*)&qs2[ty * 8 + i][kk];
                ffma2(acc[i][0], a, b2.x);
                ffma2(acc[i][1], a, b2.y);
            }
        }
        __syncthreads();
    }

    float* Sb = g_S + (size_t)b * TT * TT;
    const float scale = 11.31370849898476f;   // sqrt(128)
#pragma unroll
    for (int i = 0; i < 8; i++) {
        int t = t0 + ty * 8 + i;
        float2 p0 = *reinterpret_cast<float2*>(&acc[i][0]);
        float2 p1 = *reinterpret_cast<float2*>(&acc[i][1]);
        *(float4*)&Sb[(size_t)t * TT + s0 + tx * 4] =
            make_float4(p0.x * scale, p0.y * scale, p1.x * scale, p1.y * scale);
    }
}

// -------- K3a: per-column online max/sum over a T/8 chunk of t -------------
__global__ void colred_partial() {
    int col = blockIdx.x * 256 + threadIdx.x;   // [0, BT)
    int b = col / TT;
    int s = col % TT;
    int c = blockIdx.y;
    int t0 = c * (TT / 8);
    int t1 = t0 + (TT / 8);
    const float* Sb = g_S + (size_t)b * TT * TT;

    float m = -INFINITY, d = 0.f;
    int tstart = (s > t0) ? s : t0;
    for (int t = tstart; t < t1; t++) {
        float v = Sb[(size_t)t * TT + s];
        float nm = fmaxf(m, v);
        d = d * __expf(m - nm) + __expf(v - nm);
        m = nm;
    }
    g_pmax[c * BT + col] = m;
    g_psum[c * BT + col] = d;
}

// -------- K3b: combine 8 partials per column; store max and 1/den ----------
__global__ void colred_combine() {
    int col = blockIdx.x * 256 + threadIdx.x;
    float m = -INFINITY;
#pragma unroll
    for (int c = 0; c < 8; c++) m = fmaxf(m, g_pmax[c * BT + col]);
    float d = 0.f;
#pragma unroll
    for (int c = 0; c < 8; c++) {
        float pm = g_pmax[c * BT + col];
        float ps = g_psum[c * BT + col];
        d += ps * __expf(pm - m);      // pm=-inf,ps=0 -> 0 contribution
    }
    g_cmax[col] = m;
    g_crcp[col] = 1.f / d;
}

// ---------------- K4: out[b,t,:] = sum_s P[t,s] * v[b,s,:] -----------------
// P[t,s] = exp(S[t,s]-cmax[s]) * crcp[s] for s<=t else 0
// block 256, tile 64(t) x 128(H), s chunks 16, micro 8x4 via f32x2
__global__ void out_kernel(float* __restrict__ out) {
    int t0 = blockIdx.x * 64;
    int b  = blockIdx.y;

    __shared__ float2 wsm2[64][18];   // dup-packed P weights
    __shared__ float  vs[16][128];    // V tile, contiguous in H

    const float* Sb = g_S + (size_t)b * TT * TT;
    const float* vb = g_v + (size_t)b * TT * HH;
    const float* cmax = g_cmax + b * TT;
    const float* crcp = g_crcp + b * TT;

    int tid = threadIdx.x;
    int tx = tid & 31;      // 32 groups * 4 cols = 128 (H)
    int ty = tid >> 5;      // 8 groups * 8 rows = 64 (t)

    unsigned long long acc[8][2];
#pragma unroll
    for (int i = 0; i < 8; i++) { acc[i][0] = 0ull; acc[i][1] = 0ull; }

    int nch = (t0 + 63) / 16 + 1;           // s chunks needed (s <= t_max)
    for (int ch = 0; ch < nch; ch++) {
        int s0 = ch * 16;
#pragma unroll
        for (int i = 0; i < 4; i++) {       // weight tile 64x16, dup-packed
            int idx = i * 256 + tid;
            int r = idx >> 4, c = idx & 15;
            int t = t0 + r, s = s0 + c;
            float val = 0.f;
            if (s <= t) {
                float sc = Sb[(size_t)t * TT + s];
                val = __expf(sc - cmax[s]) * crcp[s];
            }
            wsm2[r][c] = make_float2(val, val);
        }
#pragma unroll
        for (int i = 0; i < 2; i++) {       // v tile 16x128
            int idx = tid * 2 + i;
            int r = idx >> 5, c4 = idx & 31;
            *(float4*)&vs[r][c4 * 4] = *(const float4*)&vb[(size_t)(s0 + r) * HH + c4 * 4];
        }
        __syncthreads();
#pragma unroll
        for (int kk = 0; kk < 16; kk++) {
            ulonglong2 b2 = *(const ulonglong2*)&vs[kk][tx * 4];
#pragma unroll
            for (int i = 0; i < 8; i++) {
                unsigned long long a = *(const unsigned long long*)&wsm2[ty * 8 + i][kk];
                ffma2(acc[i][0], a, b2.x);
                ffma2(acc[i][1], a, b2.y);
            }
        }
        __syncthreads();
    }
#pragma unroll
    for (int i = 0; i < 8; i++) {
        int t = t0 + ty * 8 + i;
        float2 p0 = *reinterpret_cast<float2*>(&acc[i][0]);
        float2 p1 = *reinterpret_cast<float2*>(&acc[i][1]);
        *(float4*)&out[((size_t)b * TT + t) * HH + tx * 4] =
            make_float4(p0.x, p0.y, p1.x, p1.y);
    }
}

// ---------------------------------------------------------------------------
extern "C" void kernel_launch(void* const* d_in, const int* in_sizes, int n_in,
                              void* d_out, int out_size) {
    const float* x  = (const float*)d_in[0];
    const float* Wk = (const float*)d_in[1];
    const float* Wq = (const float*)d_in[2];
    const float* Wv = (const float*)d_in[3];
    float* out = (float*)d_out;

    qkv_kernel<<<dim3(BT / 64, 3), 256>>>(x, Wk, Wq, Wv);
    score_kernel<<<dim3(TT / 128, TT / 64, BB), 256>>>();
    colred_partial<<<dim3(BT / 256, 8), 256>>>();
    colred_combine<<<BT / 256, 256>>>();
    out_kernel<<<dim3(TT / 64, BB), 256>>>(out);
}

// round 3
// speedup vs baseline: 1.2094x; 1.2094x over previous
#include <cuda_runtime.h>
#include <math.h>

#define BB 8
#define TT 2048
#define EE 1024
#define HH 128
#define BT (BB*TT)

// ---------------- scratch (device globals: allocation-free) ----------------
__device__ float g_k[BT*HH];
__device__ float g_q[BT*HH];
__device__ float g_v[BT*HH];
__device__ float g_S[(size_t)BB*TT*TT];   // S, then overwritten with E=exp(S-cmax)
__device__ float g_pmax[8*BT];
__device__ float g_psum[8*BT];
__device__ float g_cml[BT];               // cmax * log2(e)
__device__ float g_crcp[BT];              // 1/den

// ---------------- helpers --------------------------------------------------
__device__ __forceinline__ float tf32_rna(float x) {
    unsigned u;
    asm("cvt.rna.tf32.f32 %0, %1;" : "=r"(u) : "f"(x));
    return __uint_as_float(u);
}
__device__ __forceinline__ unsigned fau(float x) { return __float_as_uint(x); }

__device__ __forceinline__ void mma8(float c[4], const unsigned a[4], const unsigned b[2]) {
    asm volatile(
        "mma.sync.aligned.m16n8k8.row.col.f32.tf32.tf32.f32 "
        "{%0,%1,%2,%3}, {%4,%5,%6,%7}, {%8,%9}, {%0,%1,%2,%3};\n"
        : "+f"(c[0]), "+f"(c[1]), "+f"(c[2]), "+f"(c[3])
        : "r"(a[0]), "r"(a[1]), "r"(a[2]), "r"(a[3]), "r"(b[0]), "r"(b[1]));
}
__device__ __forceinline__ float ex2f(float y) {
    float e;
    asm("ex2.approx.f32 %0, %1;" : "=f"(e) : "f"(y));
    return e;
}

// ---------------- K1: q/k/v = x @ W  (3xTF32 mma) --------------------------
// block 256 (8 warps, 4x2), block tile 128(M)x128(N), k-chunk 16
__global__ void qkv_kernel(const float* __restrict__ x,
                           const float* __restrict__ Wk,
                           const float* __restrict__ Wq,
                           const float* __restrict__ Wv) {
    const float* W   = (blockIdx.y == 0) ? Wk : (blockIdx.y == 1) ? Wq : Wv;
    float*       outp = (blockIdx.y == 0) ? g_k : (blockIdx.y == 1) ? g_q : g_v;

    __shared__ float Ah[128][20], Al[128][20];     // x big/small, [m][k]
    __shared__ float Bh[16][140], Bl[16][140];     // W big/small, [k][n]

    int tid = threadIdx.x;
    int m0 = blockIdx.x * 128;
    int warp = tid >> 5, lane = tid & 31, g = lane >> 2, tq = lane & 3;
    int mbase = (warp >> 1) * 32, nbase = (warp & 1) * 64;

    float acc[2][8][4];
#pragma unroll
    for (int i = 0; i < 2; i++)
#pragma unroll
        for (int j = 0; j < 8; j++)
#pragma unroll
            for (int q = 0; q < 4; q++) acc[i][j][q] = 0.f;

    for (int k0 = 0; k0 < EE; k0 += 16) {
#pragma unroll
        for (int i = 0; i < 2; i++) {   // x tile 128x16
            int idx = tid * 2 + i;
            int r = idx >> 2, c4 = idx & 3;
            float4 v = *(const float4*)&x[(size_t)(m0 + r) * EE + k0 + c4 * 4];
            float4 hb = make_float4(tf32_rna(v.x), tf32_rna(v.y), tf32_rna(v.z), tf32_rna(v.w));
            *(float4*)&Ah[r][c4 * 4] = hb;
            *(float4*)&Al[r][c4 * 4] = make_float4(v.x - hb.x, v.y - hb.y, v.z - hb.z, v.w - hb.w);
        }
#pragma unroll
        for (int i = 0; i < 2; i++) {   // W tile 16x128
            int idx = tid * 2 + i;
            int r = idx >> 5, c4 = idx & 31;
            float4 v = *(const float4*)&W[(size_t)(k0 + r) * HH + c4 * 4];
            float4 hb = make_float4(tf32_rna(v.x), tf32_rna(v.y), tf32_rna(v.z), tf32_rna(v.w));
            *(float4*)&Bh[r][c4 * 4] = hb;
            *(float4*)&Bl[r][c4 * 4] = make_float4(v.x - hb.x, v.y - hb.y, v.z - hb.z, v.w - hb.w);
        }
        __syncthreads();
#pragma unroll
        for (int kk = 0; kk < 16; kk += 8) {
            unsigned ah[2][4], al[2][4];
#pragma unroll
            for (int ma = 0; ma < 2; ma++) {
                int r0 = mbase + ma * 16 + g;
                ah[ma][0] = fau(Ah[r0][kk + tq]);     ah[ma][1] = fau(Ah[r0 + 8][kk + tq]);
                ah[ma][2] = fau(Ah[r0][kk + tq + 4]); ah[ma][3] = fau(Ah[r0 + 8][kk + tq + 4]);
                al[ma][0] = fau(Al[r0][kk + tq]);     al[ma][1] = fau(Al[r0 + 8][kk + tq]);
                al[ma][2] = fau(Al[r0][kk + tq + 4]); al[ma][3] = fau(Al[r0 + 8][kk + tq + 4]);
            }
#pragma unroll
            for (int nb = 0; nb < 8; nb++) {
                int cc = nbase + nb * 8 + g;
                unsigned bh[2], bl[2];
                bh[0] = fau(Bh[kk + tq][cc]); bh[1] = fau(Bh[kk + tq + 4][cc]);
                bl[0] = fau(Bl[kk + tq][cc]); bl[1] = fau(Bl[kk + tq + 4][cc]);
#pragma unroll
                for (int ma = 0; ma < 2; ma++) {
                    mma8(acc[ma][nb], ah[ma], bh);
                    mma8(acc[ma][nb], ah[ma], bl);
                    mma8(acc[ma][nb], al[ma], bh);
                }
            }
        }
        __syncthreads();
    }
#pragma unroll
    for (int ma = 0; ma < 2; ma++)
#pragma unroll
        for (int nb = 0; nb < 8; nb++) {
            int r0 = m0 + mbase + ma * 16 + g;
            int cc = nbase + nb * 8 + 2 * tq;
            *(float2*)&outp[(size_t)r0 * HH + cc]       = make_float2(acc[ma][nb][0], acc[ma][nb][1]);
            *(float2*)&outp[(size_t)(r0 + 8) * HH + cc] = make_float2(acc[ma][nb][2], acc[ma][nb][3]);
        }
}

// ---------------- K2: S = sqrt(H) * q @ k^T  (3xTF32 mma) ------------------
// block 256, tile 128(t) x 128(s), k-dim H in chunks of 16
__global__ void score_kernel() {
    int bx = blockIdx.x, by = blockIdx.y;
    if (bx < by) return;                      // tile fully above diagonal
    int t0 = bx * 128, s0 = by * 128, b = blockIdx.z;

    __shared__ float Ah[128][20], Al[128][20];     // q big/small, [t][h]
    __shared__ float Bh[16][140], Bl[16][140];     // k^T big/small, [h][s]

    const float* qb = g_q + (size_t)b * TT * HH;
    const float* kb = g_k + (size_t)b * TT * HH;

    int tid = threadIdx.x;
    int warp = tid >> 5, lane = tid & 31, g = lane >> 2, tq = lane & 3;
    int mbase = (warp >> 1) * 32, nbase = (warp & 1) * 64;

    float acc[2][8][4];
#pragma unroll
    for (int i = 0; i < 2; i++)
#pragma unroll
        for (int j = 0; j < 8; j++)
#pragma unroll
            for (int q = 0; q < 4; q++) acc[i][j][q] = 0.f;

    for (int h0 = 0; h0 < HH; h0 += 16) {
#pragma unroll
        for (int i = 0; i < 2; i++) {   // q tile 128x16
            int idx = tid * 2 + i;
            int r = idx >> 2, c4 = idx & 3;
            float4 v = *(const float4*)&qb[(size_t)(t0 + r) * HH + h0 + c4 * 4];
            float4 hb = make_float4(tf32_rna(v.x), tf32_rna(v.y), tf32_rna(v.z), tf32_rna(v.w));
            *(float4*)&Ah[r][c4 * 4] = hb;
            *(float4*)&Al[r][c4 * 4] = make_float4(v.x - hb.x, v.y - hb.y, v.z - hb.z, v.w - hb.w);
        }
#pragma unroll
        for (int i = 0; i < 2; i++) {   // k tile 128x16 -> transposed [h][s]
            int idx = tid * 2 + i;
            int r = idx >> 2, c4 = idx & 3;
            float4 v = *(const float4*)&kb[(size_t)(s0 + r) * HH + h0 + c4 * 4];
            float vv[4] = {v.x, v.y, v.z, v.w};
#pragma unroll
            for (int j = 0; j < 4; j++) {
                float hb = tf32_rna(vv[j]);
                Bh[c4 * 4 + j][r] = hb;
                Bl[c4 * 4 + j][r] = vv[j] - hb;
            }
        }
        __syncthreads();
#pragma unroll
        for (int kk = 0; kk < 16; kk += 8) {
            unsigned ah[2][4], al[2][4];
#pragma unroll
            for (int ma = 0; ma < 2; ma++) {
                int r0 = mbase + ma * 16 + g;
                ah[ma][0] = fau(Ah[r0][kk + tq]);     ah[ma][1] = fau(Ah[r0 + 8][kk + tq]);
                ah[ma][2] = fau(Ah[r0][kk + tq + 4]); ah[ma][3] = fau(Ah[r0 + 8][kk + tq + 4]);
                al[ma][0] = fau(Al[r0][kk + tq]);     al[ma][1] = fau(Al[r0 + 8][kk + tq]);
                al[ma][2] = fau(Al[r0][kk + tq + 4]); al[ma][3] = fau(Al[r0 + 8][kk + tq + 4]);
            }
#pragma unroll
            for (int nb = 0; nb < 8; nb++) {
                int cc = nbase + nb * 8 + g;
                unsigned bh[2], bl[2];
                bh[0] = fau(Bh[kk + tq][cc]); bh[1] = fau(Bh[kk + tq + 4][cc]);
                bl[0] = fau(Bl[kk + tq][cc]); bl[1] = fau(Bl[kk + tq + 4][cc]);
#pragma unroll
                for (int ma = 0; ma < 2; ma++) {
                    mma8(acc[ma][nb], ah[ma], bh);
                    mma8(acc[ma][nb], ah[ma], bl);
                    mma8(acc[ma][nb], al[ma], bh);
                }
            }
        }
        __syncthreads();
    }

    float* Sb = g_S + (size_t)b * TT * TT;
    const float scale = 11.31370849898476f;   // sqrt(128)
#pragma unroll
    for (int ma = 0; ma < 2; ma++)
#pragma unroll
        for (int nb = 0; nb < 8; nb++) {
            int r0 = t0 + mbase + ma * 16 + g;
            int cc = s0 + nbase + nb * 8 + 2 * tq;
            *(float2*)&Sb[(size_t)r0 * TT + cc] =
                make_float2(acc[ma][nb][0] * scale, acc[ma][nb][1] * scale);
            *(float2*)&Sb[(size_t)(r0 + 8) * TT + cc] =
                make_float2(acc[ma][nb][2] * scale, acc[ma][nb][3] * scale);
        }
}

// -------- pass A: per-column partial max over a T/8 chunk (no exp) ---------
__global__ void colmax_partial() {
    int col = blockIdx.x * 256 + threadIdx.x;
    int b = col >> 11, s = col & 2047;
    int t0c = blockIdx.y * 256, t1c = t0c + 256;
    const float* Sb = g_S + (size_t)b * TT * TT;

    float m = -INFINITY;
    int t = (s > t0c) ? s : t0c;
    for (; t + 3 < t1c; t += 4) {
        float v0 = Sb[(size_t)t * TT + s];
        float v1 = Sb[(size_t)(t + 1) * TT + s];
        float v2 = Sb[(size_t)(t + 2) * TT + s];
        float v3 = Sb[(size_t)(t + 3) * TT + s];
        m = fmaxf(m, fmaxf(fmaxf(v0, v1), fmaxf(v2, v3)));
    }
    for (; t < t1c; t++) m = fmaxf(m, Sb[(size_t)t * TT + s]);
    g_pmax[blockIdx.y * BT + col] = m;
}

__global__ void colmax_combine() {
    int col = blockIdx.x * 256 + threadIdx.x;
    float m = -INFINITY;
#pragma unroll
    for (int c = 0; c < 8; c++) m = fmaxf(m, g_pmax[c * BT + col]);
    g_cml[col] = m * 1.4426950408889634f;       // cmax * log2(e)
}

// -------- pass B: E = exp(S - cmax) in place + partial column sums ---------
__global__ void expsum_partial() {
    int col = blockIdx.x * 256 + threadIdx.x;
    int b = col >> 11, s = col & 2047;
    int t0c = blockIdx.y * 256, t1c = t0c + 256;
    float* Sb = g_S + (size_t)b * TT * TT;
    float cml = g_cml[col];
    const float L = 1.4426950408889634f;

    // zero the garbage region above the diagonal inside this column's 128-block
    int z0 = s & ~127; if (z0 < t0c) z0 = t0c;
    int z1 = (s < t1c) ? s : t1c;
    for (int t = z0; t < z1; t++) Sb[(size_t)t * TT + s] = 0.f;

    float d0 = 0.f, d1 = 0.f;
    int t = (s > t0c) ? s : t0c;
    for (; t + 1 < t1c; t += 2) {
        float v0 = Sb[(size_t)t * TT + s];
        float v1 = Sb[(size_t)(t + 1) * TT + s];
        float e0 = ex2f(fmaf(v0, L, -cml));
        float e1 = ex2f(fmaf(v1, L, -cml));
        Sb[(size_t)t * TT + s] = e0;
        Sb[(size_t)(t + 1) * TT + s] = e1;
        d0 += e0; d1 += e1;
    }
    for (; t < t1c; t++) {
        float e = ex2f(fmaf(Sb[(size_t)t * TT + s], L, -cml));
        Sb[(size_t)t * TT + s] = e;
        d0 += e;
    }
    g_psum[blockIdx.y * BT + col] = d0 + d1;
}

__global__ void den_combine() {
    int col = blockIdx.x * 256 + threadIdx.x;
    float d = 0.f;
#pragma unroll
    for (int c = 0; c < 8; c++) d += g_psum[c * BT + col];
    g_crcp[col] = 1.f / d;
}

// -------- scale V rows by 1/den (fold normalizer into V) -------------------
__global__ void scale_v() {
    int idx = blockIdx.x * 256 + threadIdx.x;      // float4 index
    int row = idx >> 5;                            // HH/4 = 32 float4 per row
    float c = g_crcp[row];
    float4* p = (float4*)g_v + idx;
    float4 v = *p;
    *p = make_float4(v.x * c, v.y * c, v.z * c, v.w * c);
}

// ---------------- K4: out = E @ v'  (single-pass tf32 mma) -----------------
// block 256, tile 128(t) x 128(H), s-chunks of 16
__global__ void out_kernel(float* __restrict__ outp) {
    int t0 = blockIdx.x * 128;
    int b  = blockIdx.y;

    __shared__ float Ah[128][20];    // E tile [t][s16]
    __shared__ float Bh[16][140];    // v' tile [s16][h]

    const float* Sb = g_S + (size_t)b * TT * TT;
    const float* vb = g_v + (size_t)b * TT * HH;

    int tid = threadIdx.x;
    int warp = tid >> 5, lane = tid & 31, g = lane >> 2, tq = lane & 3;
    int mbase = (warp >> 1) * 32, nbase = (warp & 1) * 64;

    float acc[2][8][4];
#pragma unroll
    for (int i = 0; i < 2; i++)
#pragma unroll
        for (int j = 0; j < 8; j++)
#pragma unroll
            for (int q = 0; q < 4; q++) acc[i][j][q] = 0.f;

    int nch = t0 / 16 + 8;
    for (int ch = 0; ch < nch; ch++) {
        int s0 = ch * 16;
#pragma unroll
        for (int i = 0; i < 2; i++) {   // E tile 128x16
            int idx = tid * 2 + i;
            int r = idx >> 2, c4 = idx & 3;
            float4 v = *(const float4*)&Sb[(size_t)(t0 + r) * TT + s0 + c4 * 4];
            *(float4*)&Ah[r][c4 * 4] =
                make_float4(tf32_rna(v.x), tf32_rna(v.y), tf32_rna(v.z), tf32_rna(v.w));
        }
#pragma unroll
        for (int i = 0; i < 2; i++) {   // v' tile 16x128
            int idx = tid * 2 + i;
            int r = idx >> 5, c4 = idx & 31;
            float4 v = *(const float4*)&vb[(size_t)(s0 + r) * HH + c4 * 4];
            *(float4*)&Bh[r][c4 * 4] =
                make_float4(tf32_rna(v.x), tf32_rna(v.y), tf32_rna(v.z), tf32_rna(v.w));
        }
        __syncthreads();
#pragma unroll
        for (int kk = 0; kk < 16; kk += 8) {
            unsigned ah[2][4];
#pragma unroll
            for (int ma = 0; ma < 2; ma++) {
                int r0 = mbase + ma * 16 + g;
                ah[ma][0] = fau(Ah[r0][kk + tq]);     ah[ma][1] = fau(Ah[r0 + 8][kk + tq]);
                ah[ma][2] = fau(Ah[r0][kk + tq + 4]); ah[ma][3] = fau(Ah[r0 + 8][kk + tq + 4]);
            }
#pragma unroll
            for (int nb = 0; nb < 8; nb++) {
                int cc = nbase + nb * 8 + g;
                unsigned bh[2];
                bh[0] = fau(Bh[kk + tq][cc]); bh[1] = fau(Bh[kk + tq + 4][cc]);
#pragma unroll
                for (int ma = 0; ma < 2; ma++) mma8(acc[ma][nb], ah[ma], bh);
            }
        }
        __syncthreads();
    }
#pragma unroll
    for (int ma = 0; ma < 2; ma++)
#pragma unroll
        for (int nb = 0; nb < 8; nb++) {
            int r0 = t0 + mbase + ma * 16 + g;
            int cc = nbase + nb * 8 + 2 * tq;
            *(float2*)&outp[((size_t)b * TT + r0) * HH + cc] =
                make_float2(acc[ma][nb][0], acc[ma][nb][1]);
            *(float2*)&outp[((size_t)b * TT + r0 + 8) * HH + cc] =
                make_float2(acc[ma][nb][2], acc[ma][nb][3]);
        }
}

// ---------------------------------------------------------------------------
extern "C" void kernel_launch(void* const* d_in, const int* in_sizes, int n_in,
                              void* d_out, int out_size) {
    const float* x  = (const float*)d_in[0];
    const float* Wk = (const float*)d_in[1];
    const float* Wq = (const float*)d_in[2];
    const float* Wv = (const float*)d_in[3];
    float* out = (float*)d_out;

    qkv_kernel<<<dim3(BT / 128, 3), 256>>>(x, Wk, Wq, Wv);
    score_kernel<<<dim3(TT / 128, TT / 128, BB), 256>>>();
    colmax_partial<<<dim3(BT / 256, 8), 256>>>();
    colmax_combine<<<BT / 256, 256>>>();
    expsum_partial<<<dim3(BT / 256, 8), 256>>>();
    den_combine<<<BT / 256, 256>>>();
    scale_v<<<(BT * HH / 4) / 256, 256>>>();
    out_kernel<<<dim3(TT / 128, BB), 256>>>(out);
}

// round 6
// speedup vs baseline: 1.3339x; 1.1029x over previous
#include <cuda_runtime.h>
#include <math.h>

#define BB 8
#define TT 2048
#define EE 1024
#define HH 128
#define BT (BB*TT)

// ---------------- scratch (device globals: allocation-free) ----------------
__device__ float g_k[BT*HH];
__device__ float g_q[BT*HH];
__device__ float g_v[BT*HH];
__device__ float g_S[(size_t)BB*TT*TT];   // S, then overwritten with E=exp(S-cmax)
__device__ float g_pmax[8*BT];
__device__ float g_psum[8*BT];
__device__ float g_cml[BT];               // cmax * log2(e)
__device__ float g_crcp[BT];              // 1/den

// ---------------- helpers --------------------------------------------------
__device__ __forceinline__ float tf32_rna(float x) {
    unsigned u;
    asm("cvt.rna.tf32.f32 %0, %1;" : "=r"(u) : "f"(x));
    return __uint_as_float(u);
}
__device__ __forceinline__ unsigned fau(float x) { return __float_as_uint(x); }

__device__ __forceinline__ void mma8(float c[4], const unsigned a[4], const unsigned b[2]) {
    asm volatile(
        "mma.sync.aligned.m16n8k8.row.col.f32.tf32.tf32.f32 "
        "{%0,%1,%2,%3}, {%4,%5,%6,%7}, {%8,%9}, {%0,%1,%2,%3};\n"
        : "+f"(c[0]), "+f"(c[1]), "+f"(c[2]), "+f"(c[3])
        : "r"(a[0]), "r"(a[1]), "r"(a[2]), "r"(a[3]), "r"(b[0]), "r"(b[1]));
}
__device__ __forceinline__ float ex2f(float y) {
    float e;
    asm("ex2.approx.f32 %0, %1;" : "=f"(e) : "f"(y));
    return e;
}
__device__ __forceinline__ float4 cvt4(float4 v) {
    return make_float4(tf32_rna(v.x), tf32_rna(v.y), tf32_rna(v.z), tf32_rna(v.w));
}
__device__ __forceinline__ float4 sub4(float4 a, float4 b) {
    return make_float4(a.x - b.x, a.y - b.y, a.z - b.z, a.w - b.w);
}

// ---------------- K1: q/k/v = x @ W  (3xTF32, 2-stage pipeline) ------------
// block 256 (8 warps), tile 128(M) x 128(N), k-chunk 8, double-buffered
__global__ void __launch_bounds__(256) qkv_kernel(const float* __restrict__ x,
                                                  const float* __restrict__ Wk,
                                                  const float* __restrict__ Wq,
                                                  const float* __restrict__ Wv) {
    const float* W    = (blockIdx.y == 0) ? Wk : (blockIdx.y == 1) ? Wq : Wv;
    float*       outp = (blockIdx.y == 0) ? g_k : (blockIdx.y == 1) ? g_q : g_v;

    __shared__ float Ah[2][128][12], Al[2][128][12];   // x big/small  [m][k8]
    __shared__ float Bh[2][8][136],  Bl[2][8][136];    // W big/small  [k8][n]

    int tid = threadIdx.x;
    int m0 = blockIdx.x * 128;
    int warp = tid >> 5, lane = tid & 31, g = lane >> 2, tq = lane & 3;
    int mbase = (warp >> 1) * 32, nbase = (warp & 1) * 64;
    int ra = tid >> 1, ca = (tid & 1) * 4;    // A stage coords (128x8)
    int rb = tid >> 5, cb = (tid & 31) * 4;   // B stage coords (8x128)

    float acc[2][8][4];
#pragma unroll
    for (int i = 0; i < 2; i++)
#pragma unroll
        for (int j = 0; j < 8; j++)
#pragma unroll
            for (int q = 0; q < 4; q++) acc[i][j][q] = 0.f;

    float4 sA, sB;
    auto LOAD = [&](int k0) {
        sA = *(const float4*)&x[(size_t)(m0 + ra) * EE + k0 + ca];
        sB = *(const float4*)&W[(size_t)(k0 + rb) * HH + cb];
    };
    auto STORE = [&](int bsel) {
        float4 h = cvt4(sA);
        *(float4*)&Ah[bsel][ra][ca] = h;
        *(float4*)&Al[bsel][ra][ca] = sub4(sA, h);
        float4 hb = cvt4(sB);
        *(float4*)&Bh[bsel][rb][cb] = hb;
        *(float4*)&Bl[bsel][rb][cb] = sub4(sB, hb);
    };
    auto COMPUTE = [&](int bsel) {
        unsigned ah[2][4], al[2][4];
#pragma unroll
        for (int ma = 0; ma < 2; ma++) {
            int r0 = mbase + ma * 16 + g;
            ah[ma][0] = fau(Ah[bsel][r0][tq]);     ah[ma][1] = fau(Ah[bsel][r0 + 8][tq]);
            ah[ma][2] = fau(Ah[bsel][r0][tq + 4]); ah[ma][3] = fau(Ah[bsel][r0 + 8][tq + 4]);
            al[ma][0] = fau(Al[bsel][r0][tq]);     al[ma][1] = fau(Al[bsel][r0 + 8][tq]);
            al[ma][2] = fau(Al[bsel][r0][tq + 4]); al[ma][3] = fau(Al[bsel][r0 + 8][tq + 4]);
        }
#pragma unroll
        for (int nb = 0; nb < 8; nb++) {
            int cc = nbase + nb * 8 + g;
            unsigned bh[2], bl[2];
            bh[0] = fau(Bh[bsel][tq][cc]); bh[1] = fau(Bh[bsel][tq + 4][cc]);
            bl[0] = fau(Bl[bsel][tq][cc]); bl[1] = fau(Bl[bsel][tq + 4][cc]);
#pragma unroll
            for (int ma = 0; ma < 2; ma++) {
                mma8(acc[ma][nb], ah[ma], bh);
                mma8(acc[ma][nb], ah[ma], bl);
                mma8(acc[ma][nb], al[ma], bh);
            }
        }
    };

    LOAD(0); STORE(0); __syncthreads();
    const int NC = EE / 8;
    for (int c = 0; c < NC; c++) {
        if (c + 1 < NC) LOAD((c + 1) * 8);
        COMPUTE(c & 1);
        if (c + 1 < NC) STORE((c + 1) & 1);
        __syncthreads();
    }

#pragma unroll
    for (int ma = 0; ma < 2; ma++)
#pragma unroll
        for (int nb = 0; nb < 8; nb++) {
            int r0 = m0 + mbase + ma * 16 + g;
            int cc = nbase + nb * 8 + 2 * tq;
            *(float2*)&outp[(size_t)r0 * HH + cc]       = make_float2(acc[ma][nb][0], acc[ma][nb][1]);
            *(float2*)&outp[(size_t)(r0 + 8) * HH + cc] = make_float2(acc[ma][nb][2], acc[ma][nb][3]);
        }
}

// ---------------- K2: S = sqrt(H) * q @ k^T  (3xTF32, pipelined) -----------
// block 256, tile 128(t) x 128(s), k-chunk 8 over H, double-buffered
__global__ void __launch_bounds__(256) score_kernel() {
    int bx = blockIdx.x, by = blockIdx.y;
    if (bx < by) return;                      // tile fully above diagonal
    int t0 = bx * 128, s0 = by * 128, b = blockIdx.z;

    __shared__ float Ah[2][128][12], Al[2][128][12];   // q  [t][h8]
    __shared__ float Bh[2][8][136],  Bl[2][8][136];    // k^T [h8][s]

    const float* qb = g_q + (size_t)b * TT * HH;
    const float* kb = g_k + (size_t)b * TT * HH;

    int tid = threadIdx.x;
    int warp = tid >> 5, lane = tid & 31, g = lane >> 2, tq = lane & 3;
    int mbase = (warp >> 1) * 32, nbase = (warp & 1) * 64;
    int ra = tid >> 1, ca = (tid & 1) * 4;    // 128x8 stage coords

    float acc[2][8][4];
#pragma unroll
    for (int i = 0; i < 2; i++)
#pragma unroll
        for (int j = 0; j < 8; j++)
#pragma unroll
            for (int q = 0; q < 4; q++) acc[i][j][q] = 0.f;

    float4 sA, sB;
    auto LOAD = [&](int h0) {
        sA = *(const float4*)&qb[(size_t)(t0 + ra) * HH + h0 + ca];
        sB = *(const float4*)&kb[(size_t)(s0 + ra) * HH + h0 + ca];
    };
    auto STORE = [&](int bsel) {
        float4 h = cvt4(sA);
        *(float4*)&Ah[bsel][ra][ca] = h;
        *(float4*)&Al[bsel][ra][ca] = sub4(sA, h);
        // k tile transposed into [h][s]
        float vv[4] = {sB.x, sB.y, sB.z, sB.w};
#pragma unroll
        for (int j = 0; j < 4; j++) {
            float hb = tf32_rna(vv[j]);
            Bh[bsel][ca + j][ra] = hb;
            Bl[bsel][ca + j][ra] = vv[j] - hb;
        }
    };
    auto COMPUTE = [&](int bsel) {
        unsigned ah[2][4], al[2][4];
#pragma unroll
        for (int ma = 0; ma < 2; ma++) {
            int r0 = mbase + ma * 16 + g;
            ah[ma][0] = fau(Ah[bsel][r0][tq]);     ah[ma][1] = fau(Ah[bsel][r0 + 8][tq]);
            ah[ma][2] = fau(Ah[bsel][r0][tq + 4]); ah[ma][3] = fau(Ah[bsel][r0 + 8][tq + 4]);
            al[ma][0] = fau(Al[bsel][r0][tq]);     al[ma][1] = fau(Al[bsel][r0 + 8][tq]);
            al[ma][2] = fau(Al[bsel][r0][tq + 4]); al[ma][3] = fau(Al[bsel][r0 + 8][tq + 4]);
        }
#pragma unroll
        for (int nb = 0; nb < 8; nb++) {
            int cc = nbase + nb * 8 + g;
            unsigned bh[2], bl[2];
            bh[0] = fau(Bh[bsel][tq][cc]); bh[1] = fau(Bh[bsel][tq + 4][cc]);
            bl[0] = fau(Bl[bsel][tq][cc]); bl[1] = fau(Bl[bsel][tq + 4][cc]);
#pragma unroll
            for (int ma = 0; ma < 2; ma++) {
                mma8(acc[ma][nb], ah[ma], bh);
                mma8(acc[ma][nb], ah[ma], bl);
                mma8(acc[ma][nb], al[ma], bh);
            }
        }
    };

    LOAD(0); STORE(0); __syncthreads();
    const int NC = HH / 8;
    for (int c = 0; c < NC; c++) {
        if (c + 1 < NC) LOAD((c + 1) * 8);
        COMPUTE(c & 1);
        if (c + 1 < NC) STORE((c + 1) & 1);
        __syncthreads();
    }

    float* Sb = g_S + (size_t)b * TT * TT;
    const float scale = 11.31370849898476f;   // sqrt(128)
#pragma unroll
    for (int ma = 0; ma < 2; ma++)
#pragma unroll
        for (int nb = 0; nb < 8; nb++) {
            int r0 = t0 + mbase + ma * 16 + g;
            int cc = s0 + nbase + nb * 8 + 2 * tq;
            *(float2*)&Sb[(size_t)r0 * TT + cc] =
                make_float2(acc[ma][nb][0] * scale, acc[ma][nb][1] * scale);
            *(float2*)&Sb[(size_t)(r0 + 8) * TT + cc] =
                make_float2(acc[ma][nb][2] * scale, acc[ma][nb][3] * scale);
        }
}

// -------- pass A: per-column partial max over a T/8 chunk (no exp) ---------
__global__ void colmax_partial() {
    int col = blockIdx.x * 256 + threadIdx.x;
    int b = col >> 11, s = col & 2047;
    int t0c = blockIdx.y * 256, t1c = t0c + 256;
    const float* Sb = g_S + (size_t)b * TT * TT;

    float m = -INFINITY;
    int t = (s > t0c) ? s : t0c;
    for (; t + 3 < t1c; t += 4) {
        float v0 = Sb[(size_t)t * TT + s];
        float v1 = Sb[(size_t)(t + 1) * TT + s];
        float v2 = Sb[(size_t)(t + 2) * TT + s];
        float v3 = Sb[(size_t)(t + 3) * TT + s];
        m = fmaxf(m, fmaxf(fmaxf(v0, v1), fmaxf(v2, v3)));
    }
    for (; t < t1c; t++) m = fmaxf(m, Sb[(size_t)t * TT + s]);
    g_pmax[blockIdx.y * BT + col] = m;
}

__global__ void colmax_combine() {
    int col = blockIdx.x * 256 + threadIdx.x;
    float m = -INFINITY;
#pragma unroll
    for (int c = 0; c < 8; c++) m = fmaxf(m, g_pmax[c * BT + col]);
    g_cml[col] = m * 1.4426950408889634f;       // cmax * log2(e)
}

// -------- pass B: E = exp(S - cmax) in place + partial column sums ---------
__global__ void expsum_partial() {
    int col = blockIdx.x * 256 + threadIdx.x;
    int b = col >> 11, s = col & 2047;
    int t0c = blockIdx.y * 256, t1c = t0c + 256;
    float* Sb = g_S + (size_t)b * TT * TT;
    float cml = g_cml[col];
    const float L = 1.4426950408889634f;

    // zero the garbage region above the diagonal inside this column's 128-block
    int z0 = s & ~127; if (z0 < t0c) z0 = t0c;
    int z1 = (s < t1c) ? s : t1c;
    for (int t = z0; t < z1; t++) Sb[(size_t)t * TT + s] = 0.f;

    float d0 = 0.f, d1 = 0.f;
    int t = (s > t0c) ? s : t0c;
    for (; t + 1 < t1c; t += 2) {
        float v0 = Sb[(size_t)t * TT + s];
        float v1 = Sb[(size_t)(t + 1) * TT + s];
        float e0 = ex2f(fmaf(v0, L, -cml));
        float e1 = ex2f(fmaf(v1, L, -cml));
        Sb[(size_t)t * TT + s] = e0;
        Sb[(size_t)(t + 1) * TT + s] = e1;
        d0 += e0; d1 += e1;
    }
    for (; t < t1c; t++) {
        float e = ex2f(fmaf(Sb[(size_t)t * TT + s], L, -cml));
        Sb[(size_t)t * TT + s] = e;
        d0 += e;
    }
    g_psum[blockIdx.y * BT + col] = d0 + d1;
}

__global__ void den_combine() {
    int col = blockIdx.x * 256 + threadIdx.x;
    float d = 0.f;
#pragma unroll
    for (int c = 0; c < 8; c++) d += g_psum[c * BT + col];
    g_crcp[col] = 1.f / d;
}

// ---------------- K4: out = E @ (v * crcp)  (1xTF32, pipelined) ------------
// block 256, tile 128(t) x 128(H), s-chunk 8, double-buffered
__global__ void __launch_bounds__(256) out_kernel(float* __restrict__ outp) {
    int t0 = blockIdx.x * 128;
    int b  = blockIdx.y;

    __shared__ float Ah[2][128][12];    // E tile  [t][s8]
    __shared__ float Bh[2][8][136];     // v' tile [s8][h]

    const float* Sb = g_S + (size_t)b * TT * TT;
    const float* vb = g_v + (size_t)b * TT * HH;
    const float* crcp = g_crcp + b * TT;

    int tid = threadIdx.x;
    int warp = tid >> 5, lane = tid & 31, g = lane >> 2, tq = lane & 3;
    int mbase = (warp >> 1) * 32, nbase = (warp & 1) * 64;
    int ra = tid >> 1, ca = (tid & 1) * 4;    // A stage (128x8)
    int rb = tid >> 5, cb = (tid & 31) * 4;   // B stage (8x128)

    float acc[2][8][4];
#pragma unroll
    for (int i = 0; i < 2; i++)
#pragma unroll
        for (int j = 0; j < 8; j++)
#pragma unroll
            for (int q = 0; q < 4; q++) acc[i][j][q] = 0.f;

    float4 sA, sB; float sC;
    auto LOAD = [&](int s0c) {
        sA = *(const float4*)&Sb[(size_t)(t0 + ra) * TT + s0c + ca];
        sB = *(const float4*)&vb[(size_t)(s0c + rb) * HH + cb];
        sC = crcp[s0c + rb];
    };
    auto STORE = [&](int bsel) {
        *(float4*)&Ah[bsel][ra][ca] = cvt4(sA);
        float4 vsc = make_float4(sB.x * sC, sB.y * sC, sB.z * sC, sB.w * sC);
        *(float4*)&Bh[bsel][rb][cb] = cvt4(vsc);
    };
    auto COMPUTE = [&](int bsel) {
        unsigned ah[2][4];
#pragma unroll
        for (int ma = 0; ma < 2; ma++) {
            int r0 = mbase + ma * 16 + g;
            ah[ma][0] = fau(Ah[bsel][r0][tq]);     ah[ma][1] = fau(Ah[bsel][r0 + 8][tq]);
            ah[ma][2] = fau(Ah[bsel][r0][tq + 4]); ah[ma][3] = fau(Ah[bsel][r0 + 8][tq + 4]);
        }
#pragma unroll
        for (int nb = 0; nb < 8; nb++) {
            int cc = nbase + nb * 8 + g;
            unsigned bh[2];
            bh[0] = fau(Bh[bsel][tq][cc]); bh[1] = fau(Bh[bsel][tq + 4][cc]);
#pragma unroll
            for (int ma = 0; ma < 2; ma++) mma8(acc[ma][nb], ah[ma], bh);
        }
    };

    LOAD(0); STORE(0); __syncthreads();
    const int NC = t0 / 8 + 16;          // s <= t0+127
    for (int c = 0; c < NC; c++) {
        if (c + 1 < NC) LOAD((c + 1) * 8);
        COMPUTE(c & 1);
        if (c + 1 < NC) STORE((c + 1) & 1);
        __syncthreads();
    }

#pragma unroll
    for (int ma = 0; ma < 2; ma++)
#pragma unroll
        for (int nb = 0; nb < 8; nb++) {
            int r0 = t0 + mbase + ma * 16 + g;
            int cc = nbase + nb * 8 + 2 * tq;
            *(float2*)&outp[((size_t)b * TT + r0) * HH + cc] =
                make_float2(acc[ma][nb][0], acc[ma][nb][1]);
            *(float2*)&outp[((size_t)b * TT + r0 + 8) * HH + cc] =
                make_float2(acc[ma][nb][2], acc[ma][nb][3]);
        }
}

// ---------------------------------------------------------------------------
extern "C" void kernel_launch(void* const* d_in, const int* in_sizes, int n_in,
                              void* d_out, int out_size) {
    const float* x  = (const float*)d_in[0];
    const float* Wk = (const float*)d_in[1];
    const float* Wq = (const float*)d_in[2];
    const float* Wv = (const float*)d_in[3];
    float* out = (float*)d_out;

    qkv_kernel<<<dim3(BT / 128, 3), 256>>>(x, Wk, Wq, Wv);
    score_kernel<<<dim3(TT / 128, TT / 128, BB), 256>>>();
    colmax_partial<<<dim3(BT / 256, 8), 256>>>();
    colmax_combine<<<BT / 256, 256>>>();
    expsum_partial<<<dim3(BT / 256, 8), 256>>>();
    den_combine<<<BT / 256, 256>>>();
    out_kernel<<<dim3(TT / 128, BB), 256>>>(out);
}